// round 6
// baseline (speedup 1.0000x reference)
#include <cuda_runtime.h>
#include <cuda_fp16.h>
#include <cstdint>

// MultiLayerDeepSNN: 15-step LIF SNN, B=16384, layers 6->256->256->256->256->128->3.
// Round 6: round-5 design with the staging bug fixed (cp16 = 8 halfs, so each
// 16-half segment needs a cp16 pair; round 5 dropped the +8 partners).
//  - layer-1 spikes for all 15 steps precomputed in one kernel
//  - GEMM tile 256x128 (8 warps, 4m x 2n, warp tile 64x64), grid = 1 clean wave

#define NB 16384
#define THRV 1.0f

// ---------------- scratch -------------------------------------------------
__device__ __half g_spk1[15 * NB * 256];   // all-step layer1 spikes
__device__ __half g_spkA[NB * 256];
__device__ __half g_spkB[NB * 256];
__device__ float g_mem2[NB * 256];
__device__ float g_mem3[NB * 256];
__device__ float g_mem4[NB * 256];
__device__ float g_mem5[NB * 128];
// weight hi/lo: W2@0, W3@65536, W4@131072, W5@196608 (128x256)
__device__ __half g_Wh[3 * 65536 + 32768];
__device__ __half g_Wl[3 * 65536 + 32768];

// ---------------- helpers -------------------------------------------------
__device__ __forceinline__ unsigned int s2u(const void* p) {
    return (unsigned int)__cvta_generic_to_shared(p);
}
__device__ __forceinline__ void cp16(void* dst, const void* src) {
    asm volatile("cp.async.cg.shared.global [%0], [%1], 16;"
                 :: "r"(s2u(dst)), "l"(src));
}
__device__ __forceinline__ void ldmx4(unsigned int& r0, unsigned int& r1,
                                      unsigned int& r2, unsigned int& r3,
                                      unsigned int addr) {
    asm volatile("ldmatrix.sync.aligned.m8n8.x4.shared.b16 {%0,%1,%2,%3}, [%4];"
                 : "=r"(r0), "=r"(r1), "=r"(r2), "=r"(r3) : "r"(addr));
}
__device__ __forceinline__ void mma16816(float* c, const unsigned int* a,
                                         const unsigned int* b) {
    asm volatile(
        "mma.sync.aligned.m16n8k16.row.col.f32.f16.f16.f32 "
        "{%0,%1,%2,%3},{%4,%5,%6,%7},{%8,%9},{%0,%1,%2,%3};"
        : "+f"(c[0]), "+f"(c[1]), "+f"(c[2]), "+f"(c[3])
        : "r"(a[0]), "r"(a[1]), "r"(a[2]), "r"(a[3]), "r"(b[0]), "r"(b[1]));
}

// ---------------- init ----------------------------------------------------
__global__ void k_zero(float* __restrict__ out, int out_n) {
    int idx = blockIdx.x * blockDim.x + threadIdx.x;
    int stride = gridDim.x * blockDim.x;
    for (int i = idx; i < NB * 256; i += stride) {
        g_mem2[i] = 0.f; g_mem3[i] = 0.f; g_mem4[i] = 0.f;
    }
    for (int i = idx; i < NB * 128; i += stride) g_mem5[i] = 0.f;
    for (int i = idx; i < out_n; i += stride) out[i] = 0.f;
}

// ---------------- weight split: w -> hi (fp16) + lo (fp16) ----------------
__global__ void k_split(const float* __restrict__ W, __half* __restrict__ hi,
                        __half* __restrict__ lo, int n) {
    int i = blockIdx.x * blockDim.x + threadIdx.x;
    if (i < n) {
        float w = W[i];
        __half h = __float2half_rn(w);
        hi[i] = h;
        lo[i] = __float2half_rn(w - __half2float(h));
    }
}

// ---------------- layer1: cur1 + full 15-step LIF chain --------------------
__global__ void k_cur1lif(const float* __restrict__ x, const float* __restrict__ W1,
                          const float* __restrict__ b1) {
    int idx = blockIdx.x * blockDim.x + threadIdx.x;   // over NB*256
    int b = idx >> 8, o = idx & 255;
    const float* xr = x + b * 6;
    const float* wr = W1 + o * 6;
    float cur = __ldg(b1 + o);
#pragma unroll
    for (int i = 0; i < 6; i++) cur = fmaf(__ldg(xr + i), __ldg(wr + i), cur);
    float m = 0.f;
#pragma unroll
    for (int t = 0; t < 15; t++) {
        float r = (m > THRV) ? THRV : 0.f;
        m = 0.90f * m + cur - r;
        g_spk1[t * (NB * 256) + idx] = __float2half_rn(m > THRV ? 1.f : 0.f);
    }
}

// ---------------- fused tensor-core GEMM + LIF -----------------------------
// C = spk[M,256] @ W^T + b, W hi/lo fp16 [N,256] row-major (= col-major B).
// CTA tile 256x128, BK=32, 8 warps (4m x 2n), warp tile 64x64, double buffer.
// smem per buffer: A 256x40 (20KB) + Wh 128x40 (10KB) + Wl 128x40 (10KB).
#define A_H (256 * 40)
#define W_H (128 * 40)
#define BUF_H (A_H + 2 * W_H)          // 20480 halfs = 40960 B
#define SMEMB (2 * BUF_H * 2)          // 81920 B

__global__ __launch_bounds__(256, 1) void k_gemm_lif_mma(
    const __half* __restrict__ A, const __half* __restrict__ Wh,
    const __half* __restrict__ Wl, const float* __restrict__ bias,
    float* __restrict__ mem, __half* __restrict__ spk, int N, float beta) {
    extern __shared__ __half smbuf[];  // [2][BUF_H]

    const int tid = threadIdx.x;
    const int lane = tid & 31, wid = tid >> 5;
    const int wm = wid >> 1, wn = wid & 1;
    const int m0 = blockIdx.x * 256, n0 = blockIdx.y * 128;

    // global->smem mapping: segment = 16 halfs = one cp16 PAIR (base, +8).
    // A rows 0..255: thread covers (row=tid>>1, seg=(tid&1)) and (row+128, seg).
    // W rows 0..127: thread covers (row=tid>>1, seg=(tid&1)) for Wh and Wl.
    const int arow = tid >> 1;
    const int aoff = (tid & 1) * 16;   // halfs
    const __half* Ag0 = A + (size_t)(m0 + arow) * 256 + aoff;
    const __half* Ag1 = A + (size_t)(m0 + arow + 128) * 256 + aoff;
    const __half* Hg = Wh + (size_t)(n0 + arow) * 256 + aoff;
    const __half* Lg = Wl + (size_t)(n0 + arow) * 256 + aoff;
    const int sA0 = arow * 40 + aoff;
    const int sA1 = (arow + 128) * 40 + aoff;
    const int sW = arow * 40 + aoff;

    float acc[4][8][4];
#pragma unroll
    for (int i = 0; i < 4; i++)
#pragma unroll
        for (int j = 0; j < 8; j++)
#pragma unroll
            for (int q = 0; q < 4; q++) acc[i][j][q] = 0.f;

    // ldmatrix lane geometry (validated in round 3)
    const int aRowL = (lane & 15);
    const int aColL = (lane >> 4) * 8;
    const int bRowL = (lane & 7) + ((lane >> 4) & 1) * 8;
    const int bColL = ((lane >> 3) & 1) * 8;

#pragma unroll 1
    for (int kc = 0; kc < 8; ++kc) {
        int buf = kc & 1;
        if (kc == 0) {
            __half* d = smbuf;
            cp16(d + sA0, Ag0);               cp16(d + sA0 + 8, Ag0 + 8);
            cp16(d + sA1, Ag1);               cp16(d + sA1 + 8, Ag1 + 8);
            cp16(d + A_H + sW, Hg);           cp16(d + A_H + sW + 8, Hg + 8);
            cp16(d + A_H + W_H + sW, Lg);     cp16(d + A_H + W_H + sW + 8, Lg + 8);
            asm volatile("cp.async.commit_group;");
        }
        if (kc < 7) {
            int k0 = (kc + 1) * 32;
            __half* d = smbuf + (buf ^ 1) * BUF_H;
            cp16(d + sA0, Ag0 + k0);           cp16(d + sA0 + 8, Ag0 + k0 + 8);
            cp16(d + sA1, Ag1 + k0);           cp16(d + sA1 + 8, Ag1 + k0 + 8);
            cp16(d + A_H + sW, Hg + k0);       cp16(d + A_H + sW + 8, Hg + k0 + 8);
            cp16(d + A_H + W_H + sW, Lg + k0); cp16(d + A_H + W_H + sW + 8, Lg + k0 + 8);
            asm volatile("cp.async.commit_group;");
            asm volatile("cp.async.wait_group 1;");
        } else {
            asm volatile("cp.async.wait_group 0;");
        }
        __syncthreads();

        const __half* sA = smbuf + buf * BUF_H;
        const __half* sH = sA + A_H;
        const __half* sL = sH + W_H;

#pragma unroll
        for (int kk = 0; kk < 2; ++kk) {
            unsigned int aF[4][4];
#pragma unroll
            for (int mt = 0; mt < 4; mt++) {
                unsigned int ad =
                    s2u(sA + (wm * 64 + mt * 16 + aRowL) * 40 + kk * 16 + aColL);
                ldmx4(aF[mt][0], aF[mt][1], aF[mt][2], aF[mt][3], ad);
            }
            unsigned int hF[8][2], lF[8][2];
#pragma unroll
            for (int p = 0; p < 4; p++) {
                unsigned int r0, r1, r2, r3;
                unsigned int bd =
                    s2u(sH + (wn * 64 + p * 16 + bRowL) * 40 + kk * 16 + bColL);
                ldmx4(r0, r1, r2, r3, bd);
                hF[2 * p][0] = r0; hF[2 * p][1] = r1;
                hF[2 * p + 1][0] = r2; hF[2 * p + 1][1] = r3;
                unsigned int ld =
                    s2u(sL + (wn * 64 + p * 16 + bRowL) * 40 + kk * 16 + bColL);
                ldmx4(r0, r1, r2, r3, ld);
                lF[2 * p][0] = r0; lF[2 * p][1] = r1;
                lF[2 * p + 1][0] = r2; lF[2 * p + 1][1] = r3;
            }
#pragma unroll
            for (int mt = 0; mt < 4; mt++)
#pragma unroll
                for (int nt = 0; nt < 8; nt++) {
                    mma16816(acc[mt][nt], aF[mt], hF[nt]);
                    mma16816(acc[mt][nt], aF[mt], lF[nt]);
                }
        }
        __syncthreads();
    }

    // ---------------- epilogue: bias + LIF (reset from PREVIOUS mem) -------
    const int rowBase = m0 + wm * 64 + (lane >> 2);
    const int colBase = n0 + wn * 64 + (lane & 3) * 2;
#pragma unroll
    for (int mt = 0; mt < 4; mt++) {
        int r = rowBase + mt * 16;
#pragma unroll
        for (int nt = 0; nt < 8; nt++) {
            int c = colBase + nt * 8;
            size_t gi0 = (size_t)r * N + c;
            size_t gi1 = (size_t)(r + 8) * N + c;
            float2 bb = *(const float2*)(bias + c);
            float2 mp0 = *(float2*)(mem + gi0);
            float2 mp1 = *(float2*)(mem + gi1);
            float cv0 = acc[mt][nt][0] + bb.x;
            float cv1 = acc[mt][nt][1] + bb.y;
            float cv2 = acc[mt][nt][2] + bb.x;
            float cv3 = acc[mt][nt][3] + bb.y;
            float n0v = beta * mp0.x + cv0 - (mp0.x > THRV ? THRV : 0.f);
            float n1v = beta * mp0.y + cv1 - (mp0.y > THRV ? THRV : 0.f);
            float n2v = beta * mp1.x + cv2 - (mp1.x > THRV ? THRV : 0.f);
            float n3v = beta * mp1.y + cv3 - (mp1.y > THRV ? THRV : 0.f);
            *(float2*)(mem + gi0) = make_float2(n0v, n1v);
            *(float2*)(mem + gi1) = make_float2(n2v, n3v);
            __half2 s0 = __floats2half2_rn(n0v > THRV ? 1.f : 0.f,
                                           n1v > THRV ? 1.f : 0.f);
            __half2 s1 = __floats2half2_rn(n2v > THRV ? 1.f : 0.f,
                                           n3v > THRV ? 1.f : 0.f);
            *(__half2*)(spk + gi0) = s0;
            *(__half2*)(spk + gi1) = s1;
        }
    }
}

// ---------------- output stage: out += spk5 @ W6^T + b6 (N=3, K=128) -------
__global__ void k_out(const __half* __restrict__ spk5, const float* __restrict__ W6,
                      const float* __restrict__ b6, float* __restrict__ out,
                      int finalize) {
    __shared__ float w[384];
    for (int i = threadIdx.x; i < 384; i += blockDim.x) w[i] = W6[i];
    __syncthreads();
    int b = blockIdx.x * blockDim.x + threadIdx.x;
    const __half2* sp = (const __half2*)(spk5 + (size_t)b * 128);
    float s0 = __ldg(b6 + 0), s1 = __ldg(b6 + 1), s2v = __ldg(b6 + 2);
#pragma unroll 8
    for (int k = 0; k < 64; k++) {
        float2 v = __half22float2(sp[k]);
        s0 = fmaf(v.x, w[2 * k], s0);
        s0 = fmaf(v.y, w[2 * k + 1], s0);
        s1 = fmaf(v.x, w[128 + 2 * k], s1);
        s1 = fmaf(v.y, w[128 + 2 * k + 1], s1);
        s2v = fmaf(v.x, w[256 + 2 * k], s2v);
        s2v = fmaf(v.y, w[256 + 2 * k + 1], s2v);
    }
    float o0 = out[b * 3 + 0] + s0;
    float o1 = out[b * 3 + 1] + s1;
    float o2 = out[b * 3 + 2] + s2v;
    if (finalize) {
        const float inv = 1.f / 15.f;
        o0 *= inv; o1 *= inv; o2 *= inv;
    }
    out[b * 3 + 0] = o0;
    out[b * 3 + 1] = o1;
    out[b * 3 + 2] = o2;
}

// ---------------- launch --------------------------------------------------
extern "C" void kernel_launch(void* const* d_in, const int* in_sizes, int n_in,
                              void* d_out, int out_size) {
    const float* x  = (const float*)d_in[0];
    const float* W1 = (const float*)d_in[1];
    const float* b1 = (const float*)d_in[2];
    const float* W2 = (const float*)d_in[3];
    const float* b2 = (const float*)d_in[4];
    const float* W3 = (const float*)d_in[5];
    const float* b3 = (const float*)d_in[6];
    const float* W4 = (const float*)d_in[7];
    const float* b4 = (const float*)d_in[8];
    const float* W5 = (const float*)d_in[9];
    const float* b5 = (const float*)d_in[10];
    const float* W6 = (const float*)d_in[11];
    const float* b6 = (const float*)d_in[12];
    float* out = (float*)d_out;

    __half *p_spk1, *p_spkA, *p_spkB, *p_Wh, *p_Wl;
    float *p_mem2, *p_mem3, *p_mem4, *p_mem5;
    cudaGetSymbolAddress((void**)&p_spk1, g_spk1);
    cudaGetSymbolAddress((void**)&p_spkA, g_spkA);
    cudaGetSymbolAddress((void**)&p_spkB, g_spkB);
    cudaGetSymbolAddress((void**)&p_Wh, g_Wh);
    cudaGetSymbolAddress((void**)&p_Wl, g_Wl);
    cudaGetSymbolAddress((void**)&p_mem2, g_mem2);
    cudaGetSymbolAddress((void**)&p_mem3, g_mem3);
    cudaGetSymbolAddress((void**)&p_mem4, g_mem4);
    cudaGetSymbolAddress((void**)&p_mem5, g_mem5);

    cudaFuncSetAttribute(k_gemm_lif_mma, cudaFuncAttributeMaxDynamicSharedMemorySize,
                         SMEMB);

    k_zero<<<2048, 256>>>(out, out_size);
    k_split<<<(65536 + 255) / 256, 256>>>(W2, p_Wh, p_Wl, 65536);
    k_split<<<(65536 + 255) / 256, 256>>>(W3, p_Wh + 65536, p_Wl + 65536, 65536);
    k_split<<<(65536 + 255) / 256, 256>>>(W4, p_Wh + 131072, p_Wl + 131072, 65536);
    k_split<<<(32768 + 255) / 256, 256>>>(W5, p_Wh + 196608, p_Wl + 196608, 32768);
    k_cur1lif<<<NB * 256 / 256, 256>>>(x, W1, b1);

    dim3 g256(NB / 256, 2);   // N=256 stages: 64 x 2 = 128 CTAs
    dim3 g128(NB / 256, 1);   // N=128 stage:  64 CTAs

    for (int t = 0; t < 15; ++t) {
        k_gemm_lif_mma<<<g256, 256, SMEMB>>>(p_spk1 + (size_t)t * NB * 256,
                                             p_Wh, p_Wl, b2, p_mem2, p_spkB, 256, 0.88f);
        k_gemm_lif_mma<<<g256, 256, SMEMB>>>(p_spkB, p_Wh + 65536, p_Wl + 65536,
                                             b3, p_mem3, p_spkA, 256, 0.86f);
        k_gemm_lif_mma<<<g256, 256, SMEMB>>>(p_spkA, p_Wh + 131072, p_Wl + 131072,
                                             b4, p_mem4, p_spkB, 256, 0.84f);
        k_gemm_lif_mma<<<g128, 256, SMEMB>>>(p_spkB, p_Wh + 196608, p_Wl + 196608,
                                             b5, p_mem5, p_spkA, 128, 0.82f);
        k_out<<<NB / 256, 256>>>(p_spkA, W6, b6, out, t == 14 ? 1 : 0);
    }
}

// round 7
// speedup vs baseline: 1.3723x; 1.3723x over previous
#include <cuda_runtime.h>
#include <cuda_fp16.h>
#include <cstdint>

// MultiLayerDeepSNN: 15-step LIF SNN, B=16384, layers 6->256->256->256->256->128->3.
// Round 7: validated 128x128 GEMM shape (occ 2) + BK=32 + layer1 precompute +
// k_out fused into layer-5 GEMM epilogue (spk5 never touches global memory).

#define NB 16384
#define THRV 1.0f

// ---------------- scratch -------------------------------------------------
__device__ __half g_spk1[15 * NB * 256];   // all-step layer1 spikes
__device__ __half g_spkA[NB * 256];
__device__ __half g_spkB[NB * 256];
__device__ float g_mem2[NB * 256];
__device__ float g_mem3[NB * 256];
__device__ float g_mem4[NB * 256];
__device__ float g_mem5[NB * 128];
// weight hi/lo: W2@0, W3@65536, W4@131072, W5@196608 (128x256)
__device__ __half g_Wh[3 * 65536 + 32768];
__device__ __half g_Wl[3 * 65536 + 32768];

// ---------------- helpers -------------------------------------------------
__device__ __forceinline__ unsigned int s2u(const void* p) {
    return (unsigned int)__cvta_generic_to_shared(p);
}
__device__ __forceinline__ void cp16(void* dst, const void* src) {
    asm volatile("cp.async.cg.shared.global [%0], [%1], 16;"
                 :: "r"(s2u(dst)), "l"(src));
}
__device__ __forceinline__ void ldmx4(unsigned int& r0, unsigned int& r1,
                                      unsigned int& r2, unsigned int& r3,
                                      unsigned int addr) {
    asm volatile("ldmatrix.sync.aligned.m8n8.x4.shared.b16 {%0,%1,%2,%3}, [%4];"
                 : "=r"(r0), "=r"(r1), "=r"(r2), "=r"(r3) : "r"(addr));
}
__device__ __forceinline__ void mma16816(float* c, const unsigned int* a,
                                         const unsigned int* b) {
    asm volatile(
        "mma.sync.aligned.m16n8k16.row.col.f32.f16.f16.f32 "
        "{%0,%1,%2,%3},{%4,%5,%6,%7},{%8,%9},{%0,%1,%2,%3};"
        : "+f"(c[0]), "+f"(c[1]), "+f"(c[2]), "+f"(c[3])
        : "r"(a[0]), "r"(a[1]), "r"(a[2]), "r"(a[3]), "r"(b[0]), "r"(b[1]));
}

// GEMM geometry: CTA tile 128x128, BK=32, 8 warps (2m x 4n), warp tile 64x32.
// smem per buffer: A 128x40 + Wh 128x40 + Wl 128x40 halfs.
#define T_H (128 * 40)
#define BUF_H (3 * T_H)                 // 15360 halfs = 30720 B
#define SMEMB (2 * BUF_H * 2)           // 61440 B
#define SMEMB5 (SMEMB + 2048)           // + W6/b6 region for fused kernel

// ---------------- init ----------------------------------------------------
__global__ void k_zero(float* __restrict__ out, int out_n) {
    int idx = blockIdx.x * blockDim.x + threadIdx.x;
    int stride = gridDim.x * blockDim.x;
    for (int i = idx; i < NB * 256; i += stride) {
        g_mem2[i] = 0.f; g_mem3[i] = 0.f; g_mem4[i] = 0.f;
    }
    for (int i = idx; i < NB * 128; i += stride) g_mem5[i] = 0.f;
    for (int i = idx; i < out_n; i += stride) out[i] = 0.f;
}

// ---------------- weight split: w -> hi (fp16) + lo (fp16) ----------------
__global__ void k_split(const float* __restrict__ W, __half* __restrict__ hi,
                        __half* __restrict__ lo, int n) {
    int i = blockIdx.x * blockDim.x + threadIdx.x;
    if (i < n) {
        float w = W[i];
        __half h = __float2half_rn(w);
        hi[i] = h;
        lo[i] = __float2half_rn(w - __half2float(h));
    }
}

// ---------------- layer1: cur1 + full 15-step LIF chain --------------------
__global__ void k_cur1lif(const float* __restrict__ x, const float* __restrict__ W1,
                          const float* __restrict__ b1) {
    int idx = blockIdx.x * blockDim.x + threadIdx.x;   // over NB*256
    int b = idx >> 8, o = idx & 255;
    const float* xr = x + b * 6;
    const float* wr = W1 + o * 6;
    float cur = __ldg(b1 + o);
#pragma unroll
    for (int i = 0; i < 6; i++) cur = fmaf(__ldg(xr + i), __ldg(wr + i), cur);
    float m = 0.f;
#pragma unroll
    for (int t = 0; t < 15; t++) {
        float r = (m > THRV) ? THRV : 0.f;
        m = 0.90f * m + cur - r;
        g_spk1[t * (NB * 256) + idx] = __float2half_rn(m > THRV ? 1.f : 0.f);
    }
}

// ---------------- GEMM mainloop (shared by both kernels) -------------------
// Computes acc[4][4][4] for C[128,128] = A[128,256] @ W^T (hi+lo), using smbuf.
__device__ __forceinline__ void gemm_mainloop(
    const __half* __restrict__ A, const __half* __restrict__ Wh,
    const __half* __restrict__ Wl, __half* smbuf, int m0, int n0,
    int tid, int lane, int wm, int wn, float acc[4][4][4]) {
    const int arow = tid >> 1;
    const int aoff = (tid & 1) * 16;
    const __half* Ag = A + (size_t)(m0 + arow) * 256 + aoff;
    const __half* Hg = Wh + (size_t)(n0 + arow) * 256 + aoff;
    const __half* Lg = Wl + (size_t)(n0 + arow) * 256 + aoff;
    const int sOff = arow * 40 + aoff;

    const int aRowL = (lane & 15);
    const int aColL = (lane >> 4) * 8;
    const int bRowL = (lane & 7) + ((lane >> 4) & 1) * 8;
    const int bColL = ((lane >> 3) & 1) * 8;

#pragma unroll 1
    for (int kc = 0; kc < 8; ++kc) {
        int buf = kc & 1;
        if (kc == 0) {
            __half* d = smbuf;
            cp16(d + sOff, Ag);                 cp16(d + sOff + 8, Ag + 8);
            cp16(d + T_H + sOff, Hg);           cp16(d + T_H + sOff + 8, Hg + 8);
            cp16(d + 2 * T_H + sOff, Lg);       cp16(d + 2 * T_H + sOff + 8, Lg + 8);
            asm volatile("cp.async.commit_group;");
        }
        if (kc < 7) {
            int k0 = (kc + 1) * 32;
            __half* d = smbuf + (buf ^ 1) * BUF_H;
            cp16(d + sOff, Ag + k0);             cp16(d + sOff + 8, Ag + k0 + 8);
            cp16(d + T_H + sOff, Hg + k0);       cp16(d + T_H + sOff + 8, Hg + k0 + 8);
            cp16(d + 2 * T_H + sOff, Lg + k0);   cp16(d + 2 * T_H + sOff + 8, Lg + k0 + 8);
            asm volatile("cp.async.commit_group;");
            asm volatile("cp.async.wait_group 1;");
        } else {
            asm volatile("cp.async.wait_group 0;");
        }
        __syncthreads();

        const __half* sA = smbuf + buf * BUF_H;
        const __half* sH = sA + T_H;
        const __half* sL = sH + T_H;

#pragma unroll
        for (int kk = 0; kk < 2; ++kk) {
            unsigned int aF[4][4];
#pragma unroll
            for (int mt = 0; mt < 4; mt++) {
                unsigned int ad =
                    s2u(sA + (wm * 64 + mt * 16 + aRowL) * 40 + kk * 16 + aColL);
                ldmx4(aF[mt][0], aF[mt][1], aF[mt][2], aF[mt][3], ad);
            }
            unsigned int hF[4][2], lF[4][2];
#pragma unroll
            for (int p = 0; p < 2; p++) {
                unsigned int r0, r1, r2, r3;
                unsigned int bd =
                    s2u(sH + (wn * 32 + p * 16 + bRowL) * 40 + kk * 16 + bColL);
                ldmx4(r0, r1, r2, r3, bd);
                hF[2 * p][0] = r0; hF[2 * p][1] = r1;
                hF[2 * p + 1][0] = r2; hF[2 * p + 1][1] = r3;
                unsigned int ld =
                    s2u(sL + (wn * 32 + p * 16 + bRowL) * 40 + kk * 16 + bColL);
                ldmx4(r0, r1, r2, r3, ld);
                lF[2 * p][0] = r0; lF[2 * p][1] = r1;
                lF[2 * p + 1][0] = r2; lF[2 * p + 1][1] = r3;
            }
#pragma unroll
            for (int mt = 0; mt < 4; mt++)
#pragma unroll
                for (int nt = 0; nt < 4; nt++) {
                    mma16816(acc[mt][nt], aF[mt], hF[nt]);
                    mma16816(acc[mt][nt], aF[mt], lF[nt]);
                }
        }
        __syncthreads();
    }
}

// ---------------- layers 2-4: GEMM + LIF, spikes to global -----------------
__global__ __launch_bounds__(256, 2) void k_gemm_lif_mma(
    const __half* __restrict__ A, const __half* __restrict__ Wh,
    const __half* __restrict__ Wl, const float* __restrict__ bias,
    float* __restrict__ mem, __half* __restrict__ spk, int N, float beta) {
    extern __shared__ __half smbuf[];
    const int tid = threadIdx.x;
    const int lane = tid & 31, wid = tid >> 5;
    const int wm = wid >> 2, wn = wid & 3;
    const int m0 = blockIdx.x * 128, n0 = blockIdx.y * 128;

    float acc[4][4][4];
#pragma unroll
    for (int i = 0; i < 4; i++)
#pragma unroll
        for (int j = 0; j < 4; j++)
#pragma unroll
            for (int q = 0; q < 4; q++) acc[i][j][q] = 0.f;

    gemm_mainloop(A, Wh, Wl, smbuf, m0, n0, tid, lane, wm, wn, acc);

    const int rowBase = m0 + wm * 64 + (lane >> 2);
    const int colBase = n0 + wn * 32 + (lane & 3) * 2;
#pragma unroll
    for (int mt = 0; mt < 4; mt++) {
        int r = rowBase + mt * 16;
#pragma unroll
        for (int nt = 0; nt < 4; nt++) {
            int c = colBase + nt * 8;
            size_t gi0 = (size_t)r * N + c;
            size_t gi1 = (size_t)(r + 8) * N + c;
            float2 bb = *(const float2*)(bias + c);
            float2 mp0 = *(float2*)(mem + gi0);
            float2 mp1 = *(float2*)(mem + gi1);
            float cv0 = acc[mt][nt][0] + bb.x;
            float cv1 = acc[mt][nt][1] + bb.y;
            float cv2 = acc[mt][nt][2] + bb.x;
            float cv3 = acc[mt][nt][3] + bb.y;
            float n0v = beta * mp0.x + cv0 - (mp0.x > THRV ? THRV : 0.f);
            float n1v = beta * mp0.y + cv1 - (mp0.y > THRV ? THRV : 0.f);
            float n2v = beta * mp1.x + cv2 - (mp1.x > THRV ? THRV : 0.f);
            float n3v = beta * mp1.y + cv3 - (mp1.y > THRV ? THRV : 0.f);
            *(float2*)(mem + gi0) = make_float2(n0v, n1v);
            *(float2*)(mem + gi1) = make_float2(n2v, n3v);
            __half2 s0 = __floats2half2_rn(n0v > THRV ? 1.f : 0.f,
                                           n1v > THRV ? 1.f : 0.f);
            __half2 s1 = __floats2half2_rn(n2v > THRV ? 1.f : 0.f,
                                           n3v > THRV ? 1.f : 0.f);
            *(__half2*)(spk + gi0) = s0;
            *(__half2*)(spk + gi1) = s1;
        }
    }
}

// ---------------- layer 5 + output head, fully fused -----------------------
// N=128 GEMM + LIF; spk5 staged in smem only; out[b,3] += spk5[b,:] @ W6^T + b6.
__global__ __launch_bounds__(256, 2) void k_gemm5_out(
    const __half* __restrict__ A, const __half* __restrict__ Wh,
    const __half* __restrict__ Wl, const float* __restrict__ bias,
    float* __restrict__ mem, const float* __restrict__ W6,
    const float* __restrict__ b6, float* __restrict__ out,
    float beta, int finalize) {
    extern __shared__ __half smbuf[];
    float* ws = (float*)(smbuf + SMEMB / 2);   // W6 (384 floats) past gemm bufs
    const int tid = threadIdx.x;
    const int lane = tid & 31, wid = tid >> 5;
    const int wm = wid >> 2, wn = wid & 3;
    const int m0 = blockIdx.x * 128;

    // stage W6 into smem (region untouched by mainloop)
    for (int i = tid; i < 384; i += 256) ws[i] = W6[i];

    float acc[4][4][4];
#pragma unroll
    for (int i = 0; i < 4; i++)
#pragma unroll
        for (int j = 0; j < 4; j++)
#pragma unroll
            for (int q = 0; q < 4; q++) acc[i][j][q] = 0.f;

    gemm_mainloop(A, Wh, Wl, smbuf, m0, 0, tid, lane, wm, wn, acc);

    // LIF epilogue: update mem5, stage spikes in smem (row stride 132 halfs)
    const int rowL = wm * 64 + (lane >> 2);
    const int colBase = wn * 32 + (lane & 3) * 2;
#pragma unroll
    for (int mt = 0; mt < 4; mt++) {
        int rl = rowL + mt * 16;
        int r = m0 + rl;
#pragma unroll
        for (int nt = 0; nt < 4; nt++) {
            int c = colBase + nt * 8;
            size_t gi0 = (size_t)r * 128 + c;
            size_t gi1 = (size_t)(r + 8) * 128 + c;
            float2 bb = *(const float2*)(bias + c);
            float2 mp0 = *(float2*)(mem + gi0);
            float2 mp1 = *(float2*)(mem + gi1);
            float cv0 = acc[mt][nt][0] + bb.x;
            float cv1 = acc[mt][nt][1] + bb.y;
            float cv2 = acc[mt][nt][2] + bb.x;
            float cv3 = acc[mt][nt][3] + bb.y;
            float n0v = beta * mp0.x + cv0 - (mp0.x > THRV ? THRV : 0.f);
            float n1v = beta * mp0.y + cv1 - (mp0.y > THRV ? THRV : 0.f);
            float n2v = beta * mp1.x + cv2 - (mp1.x > THRV ? THRV : 0.f);
            float n3v = beta * mp1.y + cv3 - (mp1.y > THRV ? THRV : 0.f);
            *(float2*)(mem + gi0) = make_float2(n0v, n1v);
            *(float2*)(mem + gi1) = make_float2(n2v, n3v);
            smbuf[rl * 132 + c]     = __float2half_rn(n0v > THRV ? 1.f : 0.f);
            smbuf[rl * 132 + c + 1] = __float2half_rn(n1v > THRV ? 1.f : 0.f);
            smbuf[(rl + 8) * 132 + c]     = __float2half_rn(n2v > THRV ? 1.f : 0.f);
            smbuf[(rl + 8) * 132 + c + 1] = __float2half_rn(n3v > THRV ? 1.f : 0.f);
        }
    }
    __syncthreads();

    // output head: one thread per row (threads 0..127)
    if (tid < 128) {
        const __half* sr = smbuf + tid * 132;
        float s0 = __ldg(b6 + 0), s1 = __ldg(b6 + 1), s2v = __ldg(b6 + 2);
#pragma unroll 4
        for (int k = 0; k < 128; k++) {
            float v = __half2float(sr[k]);
            s0 = fmaf(v, ws[k], s0);
            s1 = fmaf(v, ws[128 + k], s1);
            s2v = fmaf(v, ws[256 + k], s2v);
        }
        int b = m0 + tid;
        float o0 = out[b * 3 + 0] + s0;
        float o1 = out[b * 3 + 1] + s1;
        float o2 = out[b * 3 + 2] + s2v;
        if (finalize) {
            const float inv = 1.f / 15.f;
            o0 *= inv; o1 *= inv; o2 *= inv;
        }
        out[b * 3 + 0] = o0;
        out[b * 3 + 1] = o1;
        out[b * 3 + 2] = o2;
    }
}

// ---------------- launch --------------------------------------------------
extern "C" void kernel_launch(void* const* d_in, const int* in_sizes, int n_in,
                              void* d_out, int out_size) {
    const float* x  = (const float*)d_in[0];
    const float* W1 = (const float*)d_in[1];
    const float* b1 = (const float*)d_in[2];
    const float* W2 = (const float*)d_in[3];
    const float* b2 = (const float*)d_in[4];
    const float* W3 = (const float*)d_in[5];
    const float* b3 = (const float*)d_in[6];
    const float* W4 = (const float*)d_in[7];
    const float* b4 = (const float*)d_in[8];
    const float* W5 = (const float*)d_in[9];
    const float* b5 = (const float*)d_in[10];
    const float* W6 = (const float*)d_in[11];
    const float* b6 = (const float*)d_in[12];
    float* out = (float*)d_out;

    __half *p_spk1, *p_spkA, *p_spkB, *p_Wh, *p_Wl;
    float *p_mem2, *p_mem3, *p_mem4, *p_mem5;
    cudaGetSymbolAddress((void**)&p_spk1, g_spk1);
    cudaGetSymbolAddress((void**)&p_spkA, g_spkA);
    cudaGetSymbolAddress((void**)&p_spkB, g_spkB);
    cudaGetSymbolAddress((void**)&p_Wh, g_Wh);
    cudaGetSymbolAddress((void**)&p_Wl, g_Wl);
    cudaGetSymbolAddress((void**)&p_mem2, g_mem2);
    cudaGetSymbolAddress((void**)&p_mem3, g_mem3);
    cudaGetSymbolAddress((void**)&p_mem4, g_mem4);
    cudaGetSymbolAddress((void**)&p_mem5, g_mem5);

    cudaFuncSetAttribute(k_gemm_lif_mma, cudaFuncAttributeMaxDynamicSharedMemorySize,
                         SMEMB);
    cudaFuncSetAttribute(k_gemm5_out, cudaFuncAttributeMaxDynamicSharedMemorySize,
                         SMEMB5);

    k_zero<<<2048, 256>>>(out, out_size);
    k_split<<<(65536 + 255) / 256, 256>>>(W2, p_Wh, p_Wl, 65536);
    k_split<<<(65536 + 255) / 256, 256>>>(W3, p_Wh + 65536, p_Wl + 65536, 65536);
    k_split<<<(65536 + 255) / 256, 256>>>(W4, p_Wh + 131072, p_Wl + 131072, 65536);
    k_split<<<(32768 + 255) / 256, 256>>>(W5, p_Wh + 196608, p_Wl + 196608, 32768);
    k_cur1lif<<<NB * 256 / 256, 256>>>(x, W1, b1);

    dim3 g256(NB / 128, 2);   // layers 2-4: 128 x 2 = 256 CTAs
    dim3 g128(NB / 128, 1);   // layer 5:    128 CTAs

    for (int t = 0; t < 15; ++t) {
        k_gemm_lif_mma<<<g256, 256, SMEMB>>>(p_spk1 + (size_t)t * NB * 256,
                                             p_Wh, p_Wl, b2, p_mem2, p_spkB, 256, 0.88f);
        k_gemm_lif_mma<<<g256, 256, SMEMB>>>(p_spkB, p_Wh + 65536, p_Wl + 65536,
                                             b3, p_mem3, p_spkA, 256, 0.86f);
        k_gemm_lif_mma<<<g256, 256, SMEMB>>>(p_spkA, p_Wh + 131072, p_Wl + 131072,
                                             b4, p_mem4, p_spkB, 256, 0.84f);
        k_gemm5_out<<<g128, 256, SMEMB5>>>(p_spkB, p_Wh + 196608, p_Wl + 196608,
                                           b5, p_mem5, W6, b6, out, 0.82f,
                                           t == 14 ? 1 : 0);
    }
}

// round 8
// speedup vs baseline: 1.3848x; 1.0091x over previous
#include <cuda_runtime.h>
#include <cuda_fp16.h>
#include <cstdint>

// MultiLayerDeepSNN: 15-step LIF SNN, B=16384, layers 6->256->256->256->256->128->3.
// Round 8: ONE persistent kernel. Inter-layer dependency is batch-row-local, so
// each CTA owns 128 batch rows and runs the whole 5-layer x 15-step chain with
// spikes living only in shared memory. Weights stream from L2 (double-buffered
// cp.async); membranes in global (L2-resident); out accumulated in registers.

#define NB 16384
#define THRV 1.0f

#define T_H  (128 * 40)        // halfs per 32-col chunk buffer (5120)
#define SA_H (8 * T_H)         // A buffer: 8 chunks = 128x256 halfs (81920 B)
#define SW_H (2 * 2 * T_H)     // W double buffer x (hi,lo)       (40960 B)
#define SMEMT ((SA_H + SW_H) * 2 + 1536)   // + W6 floats = 124416 B

// ---------------- scratch -------------------------------------------------
__device__ __half g_spk1[15 * NB * 256];   // all-step layer1 spikes
__device__ float g_mem2[NB * 256];
__device__ float g_mem3[NB * 256];
__device__ float g_mem4[NB * 256];
__device__ float g_mem5[NB * 128];
// weight hi/lo: W2@0, W3@65536, W4@131072, W5@196608 (128x256)
__device__ __half g_Wh[3 * 65536 + 32768];
__device__ __half g_Wl[3 * 65536 + 32768];

// ---------------- helpers -------------------------------------------------
__device__ __forceinline__ unsigned int s2u(const void* p) {
    return (unsigned int)__cvta_generic_to_shared(p);
}
__device__ __forceinline__ void cp16(void* dst, const void* src) {
    asm volatile("cp.async.cg.shared.global [%0], [%1], 16;"
                 :: "r"(s2u(dst)), "l"(src));
}
__device__ __forceinline__ void ldmx4(unsigned int& r0, unsigned int& r1,
                                      unsigned int& r2, unsigned int& r3,
                                      unsigned int addr) {
    asm volatile("ldmatrix.sync.aligned.m8n8.x4.shared.b16 {%0,%1,%2,%3}, [%4];"
                 : "=r"(r0), "=r"(r1), "=r"(r2), "=r"(r3) : "r"(addr));
}
__device__ __forceinline__ void mma16816(float* c, const unsigned int* a,
                                         const unsigned int* b) {
    asm volatile(
        "mma.sync.aligned.m16n8k16.row.col.f32.f16.f16.f32 "
        "{%0,%1,%2,%3},{%4,%5,%6,%7},{%8,%9},{%0,%1,%2,%3};"
        : "+f"(c[0]), "+f"(c[1]), "+f"(c[2]), "+f"(c[3])
        : "r"(a[0]), "r"(a[1]), "r"(a[2]), "r"(a[3]), "r"(b[0]), "r"(b[1]));
}

// ---------------- init ----------------------------------------------------
__global__ void k_zero() {
    int idx = blockIdx.x * blockDim.x + threadIdx.x;
    int stride = gridDim.x * blockDim.x;
    for (int i = idx; i < NB * 256; i += stride) {
        g_mem2[i] = 0.f; g_mem3[i] = 0.f; g_mem4[i] = 0.f;
    }
    for (int i = idx; i < NB * 128; i += stride) g_mem5[i] = 0.f;
}

// ---------------- weight split: w -> hi (fp16) + lo (fp16) ----------------
__global__ void k_split(const float* __restrict__ W, __half* __restrict__ hi,
                        __half* __restrict__ lo, int n) {
    int i = blockIdx.x * blockDim.x + threadIdx.x;
    if (i < n) {
        float w = W[i];
        __half h = __float2half_rn(w);
        hi[i] = h;
        lo[i] = __float2half_rn(w - __half2float(h));
    }
}

// ---------------- layer1: cur1 + full 15-step LIF chain --------------------
__global__ void k_cur1lif(const float* __restrict__ x, const float* __restrict__ W1,
                          const float* __restrict__ b1) {
    int idx = blockIdx.x * blockDim.x + threadIdx.x;   // over NB*256
    int b = idx >> 8, o = idx & 255;
    const float* xr = x + b * 6;
    const float* wr = W1 + o * 6;
    float cur = __ldg(b1 + o);
#pragma unroll
    for (int i = 0; i < 6; i++) cur = fmaf(__ldg(xr + i), __ldg(wr + i), cur);
    float m = 0.f;
#pragma unroll
    for (int t = 0; t < 15; t++) {
        float r = (m > THRV) ? THRV : 0.f;
        m = 0.90f * m + cur - r;
        g_spk1[t * (NB * 256) + idx] = __float2half_rn(m > THRV ? 1.f : 0.f);
    }
}

// ---------------- GEMM mainloop: A in smem (chunk layout), W streamed ------
// acc[4][4][4] += A[128,256](smem) @ W^T[128,256](hi+lo, global via sW).
__device__ __forceinline__ void gemm_ws(
    const __half* sA, __half* sW,
    const __half* __restrict__ Hg, const __half* __restrict__ Lg,
    int tid, int lane, int wm, int wn, float acc[4][4][4]) {
    const int wrow = tid >> 1;
    const int seg = (tid & 1) * 16;
    const __half* Hp = Hg + (size_t)wrow * 256 + seg;
    const __half* Lp = Lg + (size_t)wrow * 256 + seg;
    const int sOff = wrow * 40 + seg;
    const int aRowL = (lane & 15);
    const int aColL = (lane >> 4) * 8;
    const int bRowL = (lane & 7) + ((lane >> 4) & 1) * 8;
    const int bColL = ((lane >> 3) & 1) * 8;

#pragma unroll 1
    for (int kc = 0; kc < 8; ++kc) {
        int buf = kc & 1;
        if (kc == 0) {
            __half* d = sW;
            cp16(d + sOff, Hp);           cp16(d + sOff + 8, Hp + 8);
            cp16(d + T_H + sOff, Lp);     cp16(d + T_H + sOff + 8, Lp + 8);
            asm volatile("cp.async.commit_group;");
        }
        if (kc < 7) {
            int k0 = (kc + 1) * 32;
            __half* d = sW + (buf ^ 1) * (2 * T_H);
            cp16(d + sOff, Hp + k0);       cp16(d + sOff + 8, Hp + k0 + 8);
            cp16(d + T_H + sOff, Lp + k0); cp16(d + T_H + sOff + 8, Lp + k0 + 8);
            asm volatile("cp.async.commit_group;");
            asm volatile("cp.async.wait_group 1;");
        } else {
            asm volatile("cp.async.wait_group 0;");
        }
        __syncthreads();

        const __half* cA = sA + kc * T_H;
        const __half* sH = sW + buf * (2 * T_H);
        const __half* sL = sH + T_H;

#pragma unroll
        for (int kk = 0; kk < 2; ++kk) {
            unsigned int aF[4][4];
#pragma unroll
            for (int mt = 0; mt < 4; mt++) {
                unsigned int ad =
                    s2u(cA + (wm * 64 + mt * 16 + aRowL) * 40 + kk * 16 + aColL);
                ldmx4(aF[mt][0], aF[mt][1], aF[mt][2], aF[mt][3], ad);
            }
            unsigned int hF[4][2], lF[4][2];
#pragma unroll
            for (int p = 0; p < 2; p++) {
                unsigned int r0, r1, r2, r3;
                unsigned int bd =
                    s2u(sH + (wn * 32 + p * 16 + bRowL) * 40 + kk * 16 + bColL);
                ldmx4(r0, r1, r2, r3, bd);
                hF[2 * p][0] = r0; hF[2 * p][1] = r1;
                hF[2 * p + 1][0] = r2; hF[2 * p + 1][1] = r3;
                unsigned int ld =
                    s2u(sL + (wn * 32 + p * 16 + bRowL) * 40 + kk * 16 + bColL);
                ldmx4(r0, r1, r2, r3, ld);
                lF[2 * p][0] = r0; lF[2 * p][1] = r1;
                lF[2 * p + 1][0] = r2; lF[2 * p + 1][1] = r3;
            }
#pragma unroll
            for (int mt = 0; mt < 4; mt++)
#pragma unroll
                for (int nt = 0; nt < 4; nt++) {
                    mma16816(acc[mt][nt], aF[mt], hF[nt]);
                    mma16816(acc[mt][nt], aF[mt], lF[nt]);
                }
        }
        __syncthreads();
    }
}

// ---------------- the persistent SNN kernel --------------------------------
__global__ __launch_bounds__(256, 1) void k_snn(
    const __half* __restrict__ spk1, const __half* __restrict__ Wh,
    const __half* __restrict__ Wl,
    const float* __restrict__ b2, const float* __restrict__ b3,
    const float* __restrict__ b4, const float* __restrict__ b5,
    float* __restrict__ mem2, float* __restrict__ mem3,
    float* __restrict__ mem4, float* __restrict__ mem5,
    const float* __restrict__ W6, const float* __restrict__ b6,
    float* __restrict__ out) {
    extern __shared__ __half smbuf[];
    __half* sA = smbuf;
    __half* sW = smbuf + SA_H;
    float* ws = (float*)(smbuf + SA_H + SW_H);

    const int tid = threadIdx.x;
    const int lane = tid & 31, wid = tid >> 5;
    const int wm = wid >> 2, wn = wid & 3;
    const int m0 = blockIdx.x * 128;

    for (int i = tid; i < 384; i += 256) ws[i] = W6[i];

    const int rowL = wm * 64 + (lane >> 2);       // local row base
    const int colL = wn * 32 + (lane & 3) * 2;    // local col base within tile

    float o0 = 0.f, o1 = 0.f, o2 = 0.f;
    const float b60 = __ldg(b6 + 0), b61 = __ldg(b6 + 1), b62 = __ldg(b6 + 2);

    const __half* WhL[4] = {Wh, Wh + 65536, Wh + 131072, Wh + 196608};
    const __half* WlL[4] = {Wl, Wl + 65536, Wl + 131072, Wl + 196608};
    const float* biasL[3] = {b2, b3, b4};
    float* memL[3] = {mem2, mem3, mem4};
    const float betaL[3] = {0.88f, 0.86f, 0.84f};

#pragma unroll 1
    for (int t = 0; t < 15; ++t) {
        // ---- stage layer-1 spikes for this step into sA (chunk layout) ----
        {
            const __half* Ag = spk1 + ((size_t)t * NB + m0) * 256;
#pragma unroll
            for (int i = 0; i < 8; i++) {
                int id = i * 256 + tid;
                int c = id >> 8;
                int rr = (id >> 1) & 127;
                int sg = (id & 1) * 16;
                cp16(sA + c * T_H + rr * 40 + sg, Ag + rr * 256 + c * 32 + sg);
            }
            asm volatile("cp.async.commit_group;");
        }

        // ---- layers 2..4 (N=256: two 128-col tiles) -----------------------
#pragma unroll 1
        for (int l = 0; l < 3; l++) {
            const float beta = betaL[l];
            float* mem = memL[l];
            const float* bias = biasL[l];
            __half2 s0v[4][4][2];   // tile-0 spikes, parked in regs

#pragma unroll 1
            for (int ht = 0; ht < 2; ht++) {
                float acc[4][4][4];
#pragma unroll
                for (int i = 0; i < 4; i++)
#pragma unroll
                    for (int j = 0; j < 4; j++)
#pragma unroll
                        for (int q = 0; q < 4; q++) acc[i][j][q] = 0.f;

                gemm_ws(sA, sW, WhL[l] + ht * 128 * 256, WlL[l] + ht * 128 * 256,
                        tid, lane, wm, wn, acc);

#pragma unroll
                for (int mt = 0; mt < 4; mt++) {
                    int rl = rowL + mt * 16;
                    int r = m0 + rl;
#pragma unroll
                    for (int nt = 0; nt < 4; nt++) {
                        int c = ht * 128 + colL + nt * 8;
                        size_t gi0 = (size_t)r * 256 + c;
                        size_t gi1 = gi0 + (size_t)8 * 256;
                        float2 bb = *(const float2*)(bias + c);
                        float2 mp0 = *(float2*)(mem + gi0);
                        float2 mp1 = *(float2*)(mem + gi1);
                        float cv0 = acc[mt][nt][0] + bb.x;
                        float cv1 = acc[mt][nt][1] + bb.y;
                        float cv2 = acc[mt][nt][2] + bb.x;
                        float cv3 = acc[mt][nt][3] + bb.y;
                        float n0v = beta * mp0.x + cv0 - (mp0.x > THRV ? THRV : 0.f);
                        float n1v = beta * mp0.y + cv1 - (mp0.y > THRV ? THRV : 0.f);
                        float n2v = beta * mp1.x + cv2 - (mp1.x > THRV ? THRV : 0.f);
                        float n3v = beta * mp1.y + cv3 - (mp1.y > THRV ? THRV : 0.f);
                        *(float2*)(mem + gi0) = make_float2(n0v, n1v);
                        *(float2*)(mem + gi1) = make_float2(n2v, n3v);
                        __half2 p0 = __floats2half2_rn(n0v > THRV ? 1.f : 0.f,
                                                       n1v > THRV ? 1.f : 0.f);
                        __half2 p1 = __floats2half2_rn(n2v > THRV ? 1.f : 0.f,
                                                       n3v > THRV ? 1.f : 0.f);
                        if (ht == 0) {
                            s0v[mt][nt][0] = p0;
                            s0v[mt][nt][1] = p1;
                        } else {
                            // tile-1: sA fully consumed -> write in place
                            int cc = c & 31;
                            __half* base = sA + (c >> 5) * T_H;
                            *(__half2*)(base + rl * 40 + cc) = p0;
                            *(__half2*)(base + (rl + 8) * 40 + cc) = p1;
                        }
                    }
                }
            }
            // park tile-0 spikes into sA
#pragma unroll
            for (int mt = 0; mt < 4; mt++) {
                int rl = rowL + mt * 16;
#pragma unroll
                for (int nt = 0; nt < 4; nt++) {
                    int c = colL + nt * 8;
                    int cc = c & 31;
                    __half* base = sA + (c >> 5) * T_H;
                    *(__half2*)(base + rl * 40 + cc) = s0v[mt][nt][0];
                    *(__half2*)(base + (rl + 8) * 40 + cc) = s0v[mt][nt][1];
                }
            }
            __syncthreads();
        }

        // ---- layer 5 (N=128, one tile) + fused output head ----------------
        {
            float acc[4][4][4];
#pragma unroll
            for (int i = 0; i < 4; i++)
#pragma unroll
                for (int j = 0; j < 4; j++)
#pragma unroll
                    for (int q = 0; q < 4; q++) acc[i][j][q] = 0.f;

            gemm_ws(sA, sW, WhL[3], WlL[3], tid, lane, wm, wn, acc);

#pragma unroll
            for (int mt = 0; mt < 4; mt++) {
                int rl = rowL + mt * 16;
                int r = m0 + rl;
#pragma unroll
                for (int nt = 0; nt < 4; nt++) {
                    int c = colL + nt * 8;
                    size_t gi0 = (size_t)r * 128 + c;
                    size_t gi1 = gi0 + (size_t)8 * 128;
                    float2 bb = *(const float2*)(b5 + c);
                    float2 mp0 = *(float2*)(mem5 + gi0);
                    float2 mp1 = *(float2*)(mem5 + gi1);
                    float cv0 = acc[mt][nt][0] + bb.x;
                    float cv1 = acc[mt][nt][1] + bb.y;
                    float cv2 = acc[mt][nt][2] + bb.x;
                    float cv3 = acc[mt][nt][3] + bb.y;
                    float n0v = 0.82f * mp0.x + cv0 - (mp0.x > THRV ? THRV : 0.f);
                    float n1v = 0.82f * mp0.y + cv1 - (mp0.y > THRV ? THRV : 0.f);
                    float n2v = 0.82f * mp1.x + cv2 - (mp1.x > THRV ? THRV : 0.f);
                    float n3v = 0.82f * mp1.y + cv3 - (mp1.y > THRV ? THRV : 0.f);
                    *(float2*)(mem5 + gi0) = make_float2(n0v, n1v);
                    *(float2*)(mem5 + gi1) = make_float2(n2v, n3v);
                    int cc = c & 31;
                    __half* base = sA + (c >> 5) * T_H;
                    *(__half2*)(base + rl * 40 + cc) =
                        __floats2half2_rn(n0v > THRV ? 1.f : 0.f,
                                          n1v > THRV ? 1.f : 0.f);
                    *(__half2*)(base + (rl + 8) * 40 + cc) =
                        __floats2half2_rn(n2v > THRV ? 1.f : 0.f,
                                          n3v > THRV ? 1.f : 0.f);
                }
            }
            __syncthreads();

            if (tid < 128) {
                float s0 = b60, s1 = b61, s2v = b62;
#pragma unroll
                for (int ch = 0; ch < 4; ch++) {
                    const __half* sr = sA + ch * T_H + tid * 40;
#pragma unroll
                    for (int k = 0; k < 32; k++) {
                        float v = __half2float(sr[k]);
                        int x = ch * 32 + k;
                        s0 = fmaf(v, ws[x], s0);
                        s1 = fmaf(v, ws[128 + x], s1);
                        s2v = fmaf(v, ws[256 + x], s2v);
                    }
                }
                o0 += s0; o1 += s1; o2 += s2v;
            }
            __syncthreads();   // head done before next step overwrites sA
        }
    }

    if (tid < 128) {
        int b = m0 + tid;
        const float inv = 1.f / 15.f;
        out[b * 3 + 0] = o0 * inv;
        out[b * 3 + 1] = o1 * inv;
        out[b * 3 + 2] = o2 * inv;
    }
}

// ---------------- launch --------------------------------------------------
extern "C" void kernel_launch(void* const* d_in, const int* in_sizes, int n_in,
                              void* d_out, int out_size) {
    const float* x  = (const float*)d_in[0];
    const float* W1 = (const float*)d_in[1];
    const float* b1 = (const float*)d_in[2];
    const float* W2 = (const float*)d_in[3];
    const float* b2 = (const float*)d_in[4];
    const float* W3 = (const float*)d_in[5];
    const float* b3 = (const float*)d_in[6];
    const float* W4 = (const float*)d_in[7];
    const float* b4 = (const float*)d_in[8];
    const float* W5 = (const float*)d_in[9];
    const float* b5 = (const float*)d_in[10];
    const float* W6 = (const float*)d_in[11];
    const float* b6 = (const float*)d_in[12];
    float* out = (float*)d_out;

    __half *p_spk1, *p_Wh, *p_Wl;
    float *p_mem2, *p_mem3, *p_mem4, *p_mem5;
    cudaGetSymbolAddress((void**)&p_spk1, g_spk1);
    cudaGetSymbolAddress((void**)&p_Wh, g_Wh);
    cudaGetSymbolAddress((void**)&p_Wl, g_Wl);
    cudaGetSymbolAddress((void**)&p_mem2, g_mem2);
    cudaGetSymbolAddress((void**)&p_mem3, g_mem3);
    cudaGetSymbolAddress((void**)&p_mem4, g_mem4);
    cudaGetSymbolAddress((void**)&p_mem5, g_mem5);

    cudaFuncSetAttribute(k_snn, cudaFuncAttributeMaxDynamicSharedMemorySize, SMEMT);

    k_zero<<<2048, 256>>>();
    k_split<<<(65536 + 255) / 256, 256>>>(W2, p_Wh, p_Wl, 65536);
    k_split<<<(65536 + 255) / 256, 256>>>(W3, p_Wh + 65536, p_Wl + 65536, 65536);
    k_split<<<(65536 + 255) / 256, 256>>>(W4, p_Wh + 131072, p_Wl + 131072, 65536);
    k_split<<<(32768 + 255) / 256, 256>>>(W5, p_Wh + 196608, p_Wl + 196608, 32768);
    k_cur1lif<<<NB * 256 / 256, 256>>>(x, W1, b1);

    k_snn<<<NB / 128, 256, SMEMT>>>(p_spk1, p_Wh, p_Wl, b2, b3, b4, b5,
                                    p_mem2, p_mem3, p_mem4, p_mem5,
                                    W6, b6, out);
}

// round 10
// speedup vs baseline: 1.4891x; 1.0753x over previous
#include <cuda_runtime.h>
#include <cuda_fp16.h>
#include <cstdint>

// MultiLayerDeepSNN: 15-step LIF SNN, B=16384, layers 6->256->256->256->256->128->3.
// Round 10: round-9 design (512 threads / 16 warps, BK=64 stages, 1 sync/stage)
// with the staging bug fixed: cp16 = 8 halfs, every 16-half segment needs a PAIR.
// Spikes live in smem; weights stream from L2; membranes in global.

#define NB 16384
#define THRV 1.0f

#define T_H   (128 * 40)         // halfs per 32-col chunk (5120)
#define SA_H  (8 * T_H)          // A: 8 chunks = 128x256 halfs (81920 B)
#define SWB_H (4 * T_H)          // one W stage: 2 chunks x (hi,lo) (40960 B)
#define SW_H  (2 * SWB_H)        // double buffered (81920 B)
#define SMEMT ((SA_H + SW_H) * 2 + 1536)   // +W6 = 165376 B

// ---------------- scratch -------------------------------------------------
__device__ __half g_spk1[15 * NB * 256];
__device__ float g_mem2[NB * 256];
__device__ float g_mem3[NB * 256];
__device__ float g_mem4[NB * 256];
__device__ float g_mem5[NB * 128];
__device__ __half g_Wh[3 * 65536 + 32768];
__device__ __half g_Wl[3 * 65536 + 32768];

// ---------------- helpers -------------------------------------------------
__device__ __forceinline__ unsigned int s2u(const void* p) {
    return (unsigned int)__cvta_generic_to_shared(p);
}
__device__ __forceinline__ void cp16(void* dst, const void* src) {
    asm volatile("cp.async.cg.shared.global [%0], [%1], 16;"
                 :: "r"(s2u(dst)), "l"(src));
}
__device__ __forceinline__ void ldmx4(unsigned int& r0, unsigned int& r1,
                                      unsigned int& r2, unsigned int& r3,
                                      unsigned int addr) {
    asm volatile("ldmatrix.sync.aligned.m8n8.x4.shared.b16 {%0,%1,%2,%3}, [%4];"
                 : "=r"(r0), "=r"(r1), "=r"(r2), "=r"(r3) : "r"(addr));
}
__device__ __forceinline__ void mma16816(float* c, const unsigned int* a,
                                         const unsigned int* b) {
    asm volatile(
        "mma.sync.aligned.m16n8k16.row.col.f32.f16.f16.f32 "
        "{%0,%1,%2,%3},{%4,%5,%6,%7},{%8,%9},{%0,%1,%2,%3};"
        : "+f"(c[0]), "+f"(c[1]), "+f"(c[2]), "+f"(c[3])
        : "r"(a[0]), "r"(a[1]), "r"(a[2]), "r"(a[3]), "r"(b[0]), "r"(b[1]));
}

// ---------------- init ----------------------------------------------------
__global__ void k_zero() {
    int idx = blockIdx.x * blockDim.x + threadIdx.x;
    int stride = gridDim.x * blockDim.x;
    for (int i = idx; i < NB * 256; i += stride) {
        g_mem2[i] = 0.f; g_mem3[i] = 0.f; g_mem4[i] = 0.f;
    }
    for (int i = idx; i < NB * 128; i += stride) g_mem5[i] = 0.f;
}

// ---------------- weight split ---------------------------------------------
__global__ void k_split(const float* __restrict__ W, __half* __restrict__ hi,
                        __half* __restrict__ lo, int n) {
    int i = blockIdx.x * blockDim.x + threadIdx.x;
    if (i < n) {
        float w = W[i];
        __half h = __float2half_rn(w);
        hi[i] = h;
        lo[i] = __float2half_rn(w - __half2float(h));
    }
}

// ---------------- layer1: cur1 + full 15-step LIF chain --------------------
__global__ void k_cur1lif(const float* __restrict__ x, const float* __restrict__ W1,
                          const float* __restrict__ b1) {
    int idx = blockIdx.x * blockDim.x + threadIdx.x;
    int b = idx >> 8, o = idx & 255;
    const float* xr = x + b * 6;
    const float* wr = W1 + o * 6;
    float cur = __ldg(b1 + o);
#pragma unroll
    for (int i = 0; i < 6; i++) cur = fmaf(__ldg(xr + i), __ldg(wr + i), cur);
    float m = 0.f;
#pragma unroll
    for (int t = 0; t < 15; t++) {
        float r = (m > THRV) ? THRV : 0.f;
        m = 0.90f * m + cur - r;
        g_spk1[t * (NB * 256) + idx] = __float2half_rn(m > THRV ? 1.f : 0.f);
    }
}

// ---------------- GEMM: A resident in smem, W streamed in BK=64 stages -----
// 16 warps (4m x 4n), warp tile 32x32, acc[2][4][4].
__device__ __forceinline__ void gemm16(
    const __half* sA, __half* sW,
    const __half* __restrict__ Hg, const __half* __restrict__ Lg,
    int tid, int lane, int wm, int wn, float acc[2][4][4]) {
    const int aRowL = (lane & 15);
    const int aColL = (lane >> 4) * 8;
    const int bRowL = (lane & 7) + ((lane >> 4) & 1) * 8;
    const int bColL = ((lane >> 3) & 1) * 8;

    // stage loader: stage s covers K [s*64, s*64+64) = chunks 2s, 2s+1.
    // 1024 segment-tasks per stage; each task = cp16 PAIR (16 halfs).
    auto stageW = [&](int s, __half* dbuf) {
#pragma unroll
        for (int i = 0; i < 2; i++) {
            int id = i * 512 + tid;
            int kc2 = id >> 9;
            int hl = (id >> 8) & 1;
            int rr = (id >> 1) & 127;
            int sg = (id & 1) * 16;
            const __half* src =
                (hl ? Lg : Hg) + (size_t)rr * 256 + s * 64 + kc2 * 32 + sg;
            __half* dst = dbuf + (kc2 * 2 + hl) * T_H + rr * 40 + sg;
            cp16(dst, src);
            cp16(dst + 8, src + 8);
        }
        asm volatile("cp.async.commit_group;");
    };

    stageW(0, sW);
#pragma unroll 1
    for (int s = 0; s < 4; s++) {
        asm volatile("cp.async.wait_group 0;");
        __syncthreads();                       // buf(s) visible; buf(s-1) free
        if (s < 3) stageW(s + 1, sW + ((s + 1) & 1) * SWB_H);

        const __half* wbuf = sW + (s & 1) * SWB_H;
#pragma unroll
        for (int kc2 = 0; kc2 < 2; kc2++) {
            const __half* cA = sA + (s * 2 + kc2) * T_H;
            const __half* sH = wbuf + kc2 * 2 * T_H;
            const __half* sL = sH + T_H;
#pragma unroll
            for (int kk = 0; kk < 2; kk++) {
                unsigned int aF[2][4];
#pragma unroll
                for (int mt = 0; mt < 2; mt++) {
                    unsigned int ad =
                        s2u(cA + (wm * 32 + mt * 16 + aRowL) * 40 + kk * 16 + aColL);
                    ldmx4(aF[mt][0], aF[mt][1], aF[mt][2], aF[mt][3], ad);
                }
                unsigned int hF[4][2], lF[4][2];
#pragma unroll
                for (int p = 0; p < 2; p++) {
                    unsigned int r0, r1, r2, r3;
                    unsigned int bd =
                        s2u(sH + (wn * 32 + p * 16 + bRowL) * 40 + kk * 16 + bColL);
                    ldmx4(r0, r1, r2, r3, bd);
                    hF[2 * p][0] = r0; hF[2 * p][1] = r1;
                    hF[2 * p + 1][0] = r2; hF[2 * p + 1][1] = r3;
                    unsigned int ld =
                        s2u(sL + (wn * 32 + p * 16 + bRowL) * 40 + kk * 16 + bColL);
                    ldmx4(r0, r1, r2, r3, ld);
                    lF[2 * p][0] = r0; lF[2 * p][1] = r1;
                    lF[2 * p + 1][0] = r2; lF[2 * p + 1][1] = r3;
                }
#pragma unroll
                for (int mt = 0; mt < 2; mt++)
#pragma unroll
                    for (int nt = 0; nt < 4; nt++) {
                        mma16816(acc[mt][nt], aF[mt], hF[nt]);
                        mma16816(acc[mt][nt], aF[mt], lF[nt]);
                    }
            }
        }
    }
    __syncthreads();   // all warps done reading sA/sW before epilogue writes sA
}

// ---------------- the persistent SNN kernel --------------------------------
__global__ __launch_bounds__(512, 1) void k_snn(
    const __half* __restrict__ spk1, const __half* __restrict__ Wh,
    const __half* __restrict__ Wl,
    const float* __restrict__ b2, const float* __restrict__ b3,
    const float* __restrict__ b4, const float* __restrict__ b5,
    float* __restrict__ mem2, float* __restrict__ mem3,
    float* __restrict__ mem4, float* __restrict__ mem5,
    const float* __restrict__ W6, const float* __restrict__ b6,
    float* __restrict__ out) {
    extern __shared__ __half smbuf[];
    __half* sA = smbuf;
    __half* sW = smbuf + SA_H;
    float* ws = (float*)(smbuf + SA_H + SW_H);

    const int tid = threadIdx.x;
    const int lane = tid & 31, wid = tid >> 5;
    const int wm = wid >> 2, wn = wid & 3;     // 4m x 4n warps
    const int m0 = blockIdx.x * 128;

    for (int i = tid; i < 384; i += 512) ws[i] = W6[i];

    const int rowL = wm * 32 + (lane >> 2);
    const int colL = wn * 32 + (lane & 3) * 2;

    float o0 = 0.f, o1 = 0.f, o2 = 0.f;
    const float b60 = __ldg(b6 + 0), b61 = __ldg(b6 + 1), b62 = __ldg(b6 + 2);

    const __half* WhL[4] = {Wh, Wh + 65536, Wh + 131072, Wh + 196608};
    const __half* WlL[4] = {Wl, Wl + 65536, Wl + 131072, Wl + 196608};
    const float* biasL[3] = {b2, b3, b4};
    float* memL[3] = {mem2, mem3, mem4};
    const float betaL[3] = {0.88f, 0.86f, 0.84f};

#pragma unroll 1
    for (int t = 0; t < 15; ++t) {
        // ---- stage layer-1 spikes for this step into sA (chunk layout) ----
        // 2048 segment-tasks (8 chunks x 128 rows x 2 segs), cp16 PAIR each.
        {
            const __half* Ag = spk1 + ((size_t)t * NB + m0) * 256;
#pragma unroll
            for (int i = 0; i < 4; i++) {
                int id = i * 512 + tid;
                int c = id >> 8;
                int rr = (id >> 1) & 127;
                int sg = (id & 1) * 16;
                __half* dst = sA + c * T_H + rr * 40 + sg;
                const __half* src = Ag + rr * 256 + c * 32 + sg;
                cp16(dst, src);
                cp16(dst + 8, src + 8);
            }
            asm volatile("cp.async.commit_group;");
        }

        // ---- layers 2..4 (N=256: two 128-col tiles) -----------------------
#pragma unroll 1
        for (int l = 0; l < 3; l++) {
            const float beta = betaL[l];
            float* mem = memL[l];
            const float* bias = biasL[l];
            __half2 s0v[2][4][2];   // tile-0 spikes parked in regs

#pragma unroll 1
            for (int ht = 0; ht < 2; ht++) {
                float acc[2][4][4];
#pragma unroll
                for (int i = 0; i < 2; i++)
#pragma unroll
                    for (int j = 0; j < 4; j++)
#pragma unroll
                        for (int q = 0; q < 4; q++) acc[i][j][q] = 0.f;

                gemm16(sA, sW, WhL[l] + ht * 128 * 256, WlL[l] + ht * 128 * 256,
                       tid, lane, wm, wn, acc);

#pragma unroll
                for (int mt = 0; mt < 2; mt++) {
                    int rl = rowL + mt * 16;
                    int r = m0 + rl;
#pragma unroll
                    for (int nt = 0; nt < 4; nt++) {
                        int c = ht * 128 + colL + nt * 8;
                        size_t gi0 = (size_t)r * 256 + c;
                        size_t gi1 = gi0 + (size_t)8 * 256;
                        float2 bb = *(const float2*)(bias + c);
                        float2 mp0 = *(float2*)(mem + gi0);
                        float2 mp1 = *(float2*)(mem + gi1);
                        float cv0 = acc[mt][nt][0] + bb.x;
                        float cv1 = acc[mt][nt][1] + bb.y;
                        float cv2 = acc[mt][nt][2] + bb.x;
                        float cv3 = acc[mt][nt][3] + bb.y;
                        float n0v = beta * mp0.x + cv0 - (mp0.x > THRV ? THRV : 0.f);
                        float n1v = beta * mp0.y + cv1 - (mp0.y > THRV ? THRV : 0.f);
                        float n2v = beta * mp1.x + cv2 - (mp1.x > THRV ? THRV : 0.f);
                        float n3v = beta * mp1.y + cv3 - (mp1.y > THRV ? THRV : 0.f);
                        *(float2*)(mem + gi0) = make_float2(n0v, n1v);
                        *(float2*)(mem + gi1) = make_float2(n2v, n3v);
                        __half2 p0 = __floats2half2_rn(n0v > THRV ? 1.f : 0.f,
                                                       n1v > THRV ? 1.f : 0.f);
                        __half2 p1 = __floats2half2_rn(n2v > THRV ? 1.f : 0.f,
                                                       n3v > THRV ? 1.f : 0.f);
                        if (ht == 0) {
                            s0v[mt][nt][0] = p0;
                            s0v[mt][nt][1] = p1;
                        } else {
                            int cc = c & 31;
                            __half* base = sA + (c >> 5) * T_H;
                            *(__half2*)(base + rl * 40 + cc) = p0;
                            *(__half2*)(base + (rl + 8) * 40 + cc) = p1;
                        }
                    }
                }
            }
            // park tile-0 spikes into sA
#pragma unroll
            for (int mt = 0; mt < 2; mt++) {
                int rl = rowL + mt * 16;
#pragma unroll
                for (int nt = 0; nt < 4; nt++) {
                    int c = colL + nt * 8;
                    int cc = c & 31;
                    __half* base = sA + (c >> 5) * T_H;
                    *(__half2*)(base + rl * 40 + cc) = s0v[mt][nt][0];
                    *(__half2*)(base + (rl + 8) * 40 + cc) = s0v[mt][nt][1];
                }
            }
            __syncthreads();
        }

        // ---- layer 5 (N=128) + fused output head --------------------------
        {
            float acc[2][4][4];
#pragma unroll
            for (int i = 0; i < 2; i++)
#pragma unroll
                for (int j = 0; j < 4; j++)
#pragma unroll
                    for (int q = 0; q < 4; q++) acc[i][j][q] = 0.f;

            gemm16(sA, sW, WhL[3], WlL[3], tid, lane, wm, wn, acc);

#pragma unroll
            for (int mt = 0; mt < 2; mt++) {
                int rl = rowL + mt * 16;
                int r = m0 + rl;
#pragma unroll
                for (int nt = 0; nt < 4; nt++) {
                    int c = colL + nt * 8;
                    size_t gi0 = (size_t)r * 128 + c;
                    size_t gi1 = gi0 + (size_t)8 * 128;
                    float2 bb = *(const float2*)(b5 + c);
                    float2 mp0 = *(float2*)(mem5 + gi0);
                    float2 mp1 = *(float2*)(mem5 + gi1);
                    float cv0 = acc[mt][nt][0] + bb.x;
                    float cv1 = acc[mt][nt][1] + bb.y;
                    float cv2 = acc[mt][nt][2] + bb.x;
                    float cv3 = acc[mt][nt][3] + bb.y;
                    float n0v = 0.82f * mp0.x + cv0 - (mp0.x > THRV ? THRV : 0.f);
                    float n1v = 0.82f * mp0.y + cv1 - (mp0.y > THRV ? THRV : 0.f);
                    float n2v = 0.82f * mp1.x + cv2 - (mp1.x > THRV ? THRV : 0.f);
                    float n3v = 0.82f * mp1.y + cv3 - (mp1.y > THRV ? THRV : 0.f);
                    *(float2*)(mem5 + gi0) = make_float2(n0v, n1v);
                    *(float2*)(mem5 + gi1) = make_float2(n2v, n3v);
                    int cc = c & 31;
                    __half* base = sA + (c >> 5) * T_H;
                    *(__half2*)(base + rl * 40 + cc) =
                        __floats2half2_rn(n0v > THRV ? 1.f : 0.f,
                                          n1v > THRV ? 1.f : 0.f);
                    *(__half2*)(base + (rl + 8) * 40 + cc) =
                        __floats2half2_rn(n2v > THRV ? 1.f : 0.f,
                                          n3v > THRV ? 1.f : 0.f);
                }
            }
            __syncthreads();

            if (tid < 128) {
                float s0 = b60, s1 = b61, s2v = b62;
#pragma unroll
                for (int ch = 0; ch < 4; ch++) {
                    const __half* sr = sA + ch * T_H + tid * 40;
#pragma unroll
                    for (int k = 0; k < 32; k++) {
                        float v = __half2float(sr[k]);
                        int x = ch * 32 + k;
                        s0 = fmaf(v, ws[x], s0);
                        s1 = fmaf(v, ws[128 + x], s1);
                        s2v = fmaf(v, ws[256 + x], s2v);
                    }
                }
                o0 += s0; o1 += s1; o2 += s2v;
            }
            __syncthreads();   // head done before next step's A staging
        }
    }

    if (tid < 128) {
        int b = m0 + tid;
        const float inv = 1.f / 15.f;
        out[b * 3 + 0] = o0 * inv;
        out[b * 3 + 1] = o1 * inv;
        out[b * 3 + 2] = o2 * inv;
    }
}

// ---------------- launch --------------------------------------------------
extern "C" void kernel_launch(void* const* d_in, const int* in_sizes, int n_in,
                              void* d_out, int out_size) {
    const float* x  = (const float*)d_in[0];
    const float* W1 = (const float*)d_in[1];
    const float* b1 = (const float*)d_in[2];
    const float* W2 = (const float*)d_in[3];
    const float* b2 = (const float*)d_in[4];
    const float* W3 = (const float*)d_in[5];
    const float* b3 = (const float*)d_in[6];
    const float* W4 = (const float*)d_in[7];
    const float* b4 = (const float*)d_in[8];
    const float* W5 = (const float*)d_in[9];
    const float* b5 = (const float*)d_in[10];
    const float* W6 = (const float*)d_in[11];
    const float* b6 = (const float*)d_in[12];
    float* out = (float*)d_out;

    __half *p_spk1, *p_Wh, *p_Wl;
    float *p_mem2, *p_mem3, *p_mem4, *p_mem5;
    cudaGetSymbolAddress((void**)&p_spk1, g_spk1);
    cudaGetSymbolAddress((void**)&p_Wh, g_Wh);
    cudaGetSymbolAddress((void**)&p_Wl, g_Wl);
    cudaGetSymbolAddress((void**)&p_mem2, g_mem2);
    cudaGetSymbolAddress((void**)&p_mem3, g_mem3);
    cudaGetSymbolAddress((void**)&p_mem4, g_mem4);
    cudaGetSymbolAddress((void**)&p_mem5, g_mem5);

    cudaFuncSetAttribute(k_snn, cudaFuncAttributeMaxDynamicSharedMemorySize, SMEMT);

    k_zero<<<2048, 256>>>();
    k_split<<<(65536 + 255) / 256, 256>>>(W2, p_Wh, p_Wl, 65536);
    k_split<<<(65536 + 255) / 256, 256>>>(W3, p_Wh + 65536, p_Wl + 65536, 65536);
    k_split<<<(65536 + 255) / 256, 256>>>(W4, p_Wh + 131072, p_Wl + 131072, 65536);
    k_split<<<(32768 + 255) / 256, 256>>>(W5, p_Wh + 196608, p_Wl + 196608, 32768);
    k_cur1lif<<<NB * 256 / 256, 256>>>(x, W1, b1);

    k_snn<<<NB / 128, 512, SMEMT>>>(p_spk1, p_Wh, p_Wl, b2, b3, b4, b5,
                                    p_mem2, p_mem3, p_mem4, p_mem5,
                                    W6, b6, out);
}

// round 11
// speedup vs baseline: 1.5251x; 1.0242x over previous
#include <cuda_runtime.h>
#include <cuda_fp16.h>
#include <cstdint>

// MultiLayerDeepSNN: 15-step LIF SNN, B=16384, layers 6->256->256->256->256->128->3.
// Round 11: round-10 kernel + (a) cross-tile weight stage-0 prefetch (issued at
// s==3 into the freed buffer, overlapping stage-3 compute + epilogue), and
// (b) all setup merged into ONE kernel (2 launches total -> ncu hits k_snn).

#define NB 16384
#define THRV 1.0f

#define T_H   (128 * 40)         // halfs per 32-col chunk (5120)
#define SA_H  (8 * T_H)          // A: 8 chunks = 128x256 halfs (81920 B)
#define SWB_H (4 * T_H)          // one W stage: 2 chunks x (hi,lo) (40960 B)
#define SW_H  (2 * SWB_H)        // double buffered (81920 B)
#define SMEMT ((SA_H + SW_H) * 2 + 1536)   // +W6 = 165376 B

// ---------------- scratch -------------------------------------------------
__device__ __half g_spk1[15 * NB * 256];
__device__ float g_mem2[NB * 256];
__device__ float g_mem3[NB * 256];
__device__ float g_mem4[NB * 256];
__device__ float g_mem5[NB * 128];
__device__ __half g_Wh[3 * 65536 + 32768];
__device__ __half g_Wl[3 * 65536 + 32768];

// ---------------- helpers -------------------------------------------------
__device__ __forceinline__ unsigned int s2u(const void* p) {
    return (unsigned int)__cvta_generic_to_shared(p);
}
__device__ __forceinline__ void cp16(void* dst, const void* src) {
    asm volatile("cp.async.cg.shared.global [%0], [%1], 16;"
                 :: "r"(s2u(dst)), "l"(src));
}
__device__ __forceinline__ void ldmx4(unsigned int& r0, unsigned int& r1,
                                      unsigned int& r2, unsigned int& r3,
                                      unsigned int addr) {
    asm volatile("ldmatrix.sync.aligned.m8n8.x4.shared.b16 {%0,%1,%2,%3}, [%4];"
                 : "=r"(r0), "=r"(r1), "=r"(r2), "=r"(r3) : "r"(addr));
}
__device__ __forceinline__ void mma16816(float* c, const unsigned int* a,
                                         const unsigned int* b) {
    asm volatile(
        "mma.sync.aligned.m16n8k16.row.col.f32.f16.f16.f32 "
        "{%0,%1,%2,%3},{%4,%5,%6,%7},{%8,%9},{%0,%1,%2,%3};"
        : "+f"(c[0]), "+f"(c[1]), "+f"(c[2]), "+f"(c[3])
        : "r"(a[0]), "r"(a[1]), "r"(a[2]), "r"(a[3]), "r"(b[0]), "r"(b[1]));
}

// stage loader: stage s covers K [s*64, s*64+64) = chunks 2s, 2s+1 of W (hi+lo).
// 1024 segment-tasks; each = cp16 PAIR (16 halfs). Audited: 1024*16 = 16384 halfs
// = 2 chunks * 2 (hi/lo) * 128 rows * 32 halfs.
__device__ __forceinline__ void stage_load(__half* dbuf, const __half* Hg,
                                           const __half* Lg, int s, int tid) {
#pragma unroll
    for (int i = 0; i < 2; i++) {
        int id = i * 512 + tid;
        int kc2 = id >> 9;
        int hl = (id >> 8) & 1;
        int rr = (id >> 1) & 127;
        int sg = (id & 1) * 16;
        const __half* src =
            (hl ? Lg : Hg) + (size_t)rr * 256 + s * 64 + kc2 * 32 + sg;
        __half* dst = dbuf + (kc2 * 2 + hl) * T_H + rr * 40 + sg;
        cp16(dst, src);
        cp16(dst + 8, src + 8);
    }
    asm volatile("cp.async.commit_group;");
}

// ---------------- merged setup: zero mems + split weights + layer1 chain ---
__global__ void k_setup(const float* __restrict__ x, const float* __restrict__ W1,
                        const float* __restrict__ b1,
                        const float* __restrict__ W2, const float* __restrict__ W3,
                        const float* __restrict__ W4, const float* __restrict__ W5) {
    int idx = blockIdx.x * blockDim.x + threadIdx.x;
    int stride = gridDim.x * blockDim.x;
    for (int i = idx; i < NB * 256; i += stride) {
        g_mem2[i] = 0.f; g_mem3[i] = 0.f; g_mem4[i] = 0.f;
    }
    for (int i = idx; i < NB * 128; i += stride) g_mem5[i] = 0.f;

    for (int i = idx; i < 65536; i += stride) {
        float w = W2[i]; __half h = __float2half_rn(w);
        g_Wh[i] = h; g_Wl[i] = __float2half_rn(w - __half2float(h));
        w = W3[i]; h = __float2half_rn(w);
        g_Wh[65536 + i] = h; g_Wl[65536 + i] = __float2half_rn(w - __half2float(h));
        w = W4[i]; h = __float2half_rn(w);
        g_Wh[131072 + i] = h; g_Wl[131072 + i] = __float2half_rn(w - __half2float(h));
    }
    for (int i = idx; i < 32768; i += stride) {
        float w = W5[i]; __half h = __float2half_rn(w);
        g_Wh[196608 + i] = h; g_Wl[196608 + i] = __float2half_rn(w - __half2float(h));
    }

    for (int i = idx; i < NB * 256; i += stride) {
        int b = i >> 8, o = i & 255;
        const float* xr = x + b * 6;
        const float* wr = W1 + o * 6;
        float cur = __ldg(b1 + o);
#pragma unroll
        for (int j = 0; j < 6; j++) cur = fmaf(__ldg(xr + j), __ldg(wr + j), cur);
        float m = 0.f;
#pragma unroll
        for (int t = 0; t < 15; t++) {
            float r = (m > THRV) ? THRV : 0.f;
            m = 0.90f * m + cur - r;
            g_spk1[t * (NB * 256) + i] = __float2half_rn(m > THRV ? 1.f : 0.f);
        }
    }
}

// ---------------- GEMM: A resident in smem, W streamed in BK=64 stages -----
// 16 warps (4m x 4n), warp tile 32x32, acc[2][4][4].
// pre: stage-0 already in flight (prefetched by previous tile).
// nH/nL: next tile's weights; stage-0 prefetched into buf0 at s==3 (overlaps
// stage-3 compute + epilogue). Entry wait_group 0 covers all outstanding groups.
__device__ __forceinline__ void gemm16(
    const __half* sA, __half* sW,
    const __half* __restrict__ Hg, const __half* __restrict__ Lg,
    const __half* nH, const __half* nL, int pre,
    int tid, int lane, int wm, int wn, float acc[2][4][4]) {
    const int aRowL = (lane & 15);
    const int aColL = (lane >> 4) * 8;
    const int bRowL = (lane & 7) + ((lane >> 4) & 1) * 8;
    const int bColL = ((lane >> 3) & 1) * 8;

    if (!pre) stage_load(sW, Hg, Lg, 0, tid);

#pragma unroll 1
    for (int s = 0; s < 4; s++) {
        asm volatile("cp.async.wait_group 0;");
        __syncthreads();                       // buf(s) visible; buf(s^1) free
        if (s < 3) {
            stage_load(sW + ((s + 1) & 1) * SWB_H, Hg, Lg, s + 1, tid);
        } else if (nH) {
            stage_load(sW, nH, nL, 0, tid);    // next tile's stage-0 into buf0
        }

        const __half* wbuf = sW + (s & 1) * SWB_H;
#pragma unroll
        for (int kc2 = 0; kc2 < 2; kc2++) {
            const __half* cA = sA + (s * 2 + kc2) * T_H;
            const __half* sH = wbuf + kc2 * 2 * T_H;
            const __half* sL = sH + T_H;
#pragma unroll
            for (int kk = 0; kk < 2; kk++) {
                unsigned int aF[2][4];
#pragma unroll
                for (int mt = 0; mt < 2; mt++) {
                    unsigned int ad =
                        s2u(cA + (wm * 32 + mt * 16 + aRowL) * 40 + kk * 16 + aColL);
                    ldmx4(aF[mt][0], aF[mt][1], aF[mt][2], aF[mt][3], ad);
                }
                unsigned int hF[4][2], lF[4][2];
#pragma unroll
                for (int p = 0; p < 2; p++) {
                    unsigned int r0, r1, r2, r3;
                    unsigned int bd =
                        s2u(sH + (wn * 32 + p * 16 + bRowL) * 40 + kk * 16 + bColL);
                    ldmx4(r0, r1, r2, r3, bd);
                    hF[2 * p][0] = r0; hF[2 * p][1] = r1;
                    hF[2 * p + 1][0] = r2; hF[2 * p + 1][1] = r3;
                    unsigned int ld =
                        s2u(sL + (wn * 32 + p * 16 + bRowL) * 40 + kk * 16 + bColL);
                    ldmx4(r0, r1, r2, r3, ld);
                    lF[2 * p][0] = r0; lF[2 * p][1] = r1;
                    lF[2 * p + 1][0] = r2; lF[2 * p + 1][1] = r3;
                }
#pragma unroll
                for (int mt = 0; mt < 2; mt++)
#pragma unroll
                    for (int nt = 0; nt < 4; nt++) {
                        mma16816(acc[mt][nt], aF[mt], hF[nt]);
                        mma16816(acc[mt][nt], aF[mt], lF[nt]);
                    }
            }
        }
    }
    __syncthreads();   // all warps done reading sA/sW before epilogue writes sA
}

// ---------------- the persistent SNN kernel --------------------------------
__global__ __launch_bounds__(512, 1) void k_snn(
    const __half* __restrict__ spk1, const __half* __restrict__ Wh,
    const __half* __restrict__ Wl,
    const float* __restrict__ b2, const float* __restrict__ b3,
    const float* __restrict__ b4, const float* __restrict__ b5,
    float* __restrict__ mem2, float* __restrict__ mem3,
    float* __restrict__ mem4, float* __restrict__ mem5,
    const float* __restrict__ W6, const float* __restrict__ b6,
    float* __restrict__ out) {
    extern __shared__ __half smbuf[];
    __half* sA = smbuf;
    __half* sW = smbuf + SA_H;
    float* ws = (float*)(smbuf + SA_H + SW_H);

    const int tid = threadIdx.x;
    const int lane = tid & 31, wid = tid >> 5;
    const int wm = wid >> 2, wn = wid & 3;     // 4m x 4n warps
    const int m0 = blockIdx.x * 128;

    for (int i = tid; i < 384; i += 512) ws[i] = W6[i];

    const int rowL = wm * 32 + (lane >> 2);
    const int colL = wn * 32 + (lane & 3) * 2;

    float o0 = 0.f, o1 = 0.f, o2 = 0.f;
    const float b60 = __ldg(b6 + 0), b61 = __ldg(b6 + 1), b62 = __ldg(b6 + 2);

    const __half* WhL[4] = {Wh, Wh + 65536, Wh + 131072, Wh + 196608};
    const __half* WlL[4] = {Wl, Wl + 65536, Wl + 131072, Wl + 196608};
    const float* biasL[3] = {b2, b3, b4};
    float* memL[3] = {mem2, mem3, mem4};
    const float betaL[3] = {0.88f, 0.86f, 0.84f};

    // tile schedule per step: (l=0,h0)(l=0,h1)(l=1,h0)(l=1,h1)(l=2,h0)(l=2,h1)(l5)
    // next tile after l5 = next step's (l=0,h0).
    int pre = 0;   // first gemm of the kernel has no prefetch

#pragma unroll 1
    for (int t = 0; t < 15; ++t) {
        // ---- stage layer-1 spikes for this step into sA (chunk layout) ----
        // 2048 tasks (8 chunks x 128 rows x 2 segs), cp16 PAIR each.
        {
            const __half* Ag = spk1 + ((size_t)t * NB + m0) * 256;
#pragma unroll
            for (int i = 0; i < 4; i++) {
                int id = i * 512 + tid;
                int c = id >> 8;
                int rr = (id >> 1) & 127;
                int sg = (id & 1) * 16;
                __half* dst = sA + c * T_H + rr * 40 + sg;
                const __half* src = Ag + rr * 256 + c * 32 + sg;
                cp16(dst, src);
                cp16(dst + 8, src + 8);
            }
            asm volatile("cp.async.commit_group;");
        }

        // ---- layers 2..4 (N=256: two 128-col tiles) -----------------------
#pragma unroll 1
        for (int l = 0; l < 3; l++) {
            const float beta = betaL[l];
            float* mem = memL[l];
            const float* bias = biasL[l];
            __half2 s0v[2][4][2];   // tile-0 spikes parked in regs

#pragma unroll 1
            for (int ht = 0; ht < 2; ht++) {
                // next tile in schedule
                const __half *nH, *nL;
                if (ht == 0) { nH = WhL[l] + 128 * 256; nL = WlL[l] + 128 * 256; }
                else if (l < 2) { nH = WhL[l + 1]; nL = WlL[l + 1]; }
                else { nH = WhL[3]; nL = WlL[3]; }

                float acc[2][4][4];
#pragma unroll
                for (int i = 0; i < 2; i++)
#pragma unroll
                    for (int j = 0; j < 4; j++)
#pragma unroll
                        for (int q = 0; q < 4; q++) acc[i][j][q] = 0.f;

                gemm16(sA, sW, WhL[l] + ht * 128 * 256, WlL[l] + ht * 128 * 256,
                       nH, nL, pre, tid, lane, wm, wn, acc);
                pre = 1;

#pragma unroll
                for (int mt = 0; mt < 2; mt++) {
                    int rl = rowL + mt * 16;
                    int r = m0 + rl;
#pragma unroll
                    for (int nt = 0; nt < 4; nt++) {
                        int c = ht * 128 + colL + nt * 8;
                        size_t gi0 = (size_t)r * 256 + c;
                        size_t gi1 = gi0 + (size_t)8 * 256;
                        float2 bb = *(const float2*)(bias + c);
                        float2 mp0 = *(float2*)(mem + gi0);
                        float2 mp1 = *(float2*)(mem + gi1);
                        float cv0 = acc[mt][nt][0] + bb.x;
                        float cv1 = acc[mt][nt][1] + bb.y;
                        float cv2 = acc[mt][nt][2] + bb.x;
                        float cv3 = acc[mt][nt][3] + bb.y;
                        float n0v = beta * mp0.x + cv0 - (mp0.x > THRV ? THRV : 0.f);
                        float n1v = beta * mp0.y + cv1 - (mp0.y > THRV ? THRV : 0.f);
                        float n2v = beta * mp1.x + cv2 - (mp1.x > THRV ? THRV : 0.f);
                        float n3v = beta * mp1.y + cv3 - (mp1.y > THRV ? THRV : 0.f);
                        *(float2*)(mem + gi0) = make_float2(n0v, n1v);
                        *(float2*)(mem + gi1) = make_float2(n2v, n3v);
                        __half2 p0 = __floats2half2_rn(n0v > THRV ? 1.f : 0.f,
                                                       n1v > THRV ? 1.f : 0.f);
                        __half2 p1 = __floats2half2_rn(n2v > THRV ? 1.f : 0.f,
                                                       n3v > THRV ? 1.f : 0.f);
                        if (ht == 0) {
                            s0v[mt][nt][0] = p0;
                            s0v[mt][nt][1] = p1;
                        } else {
                            int cc = c & 31;
                            __half* base = sA + (c >> 5) * T_H;
                            *(__half2*)(base + rl * 40 + cc) = p0;
                            *(__half2*)(base + (rl + 8) * 40 + cc) = p1;
                        }
                    }
                }
            }
            // park tile-0 spikes into sA
#pragma unroll
            for (int mt = 0; mt < 2; mt++) {
                int rl = rowL + mt * 16;
#pragma unroll
                for (int nt = 0; nt < 4; nt++) {
                    int c = colL + nt * 8;
                    int cc = c & 31;
                    __half* base = sA + (c >> 5) * T_H;
                    *(__half2*)(base + rl * 40 + cc) = s0v[mt][nt][0];
                    *(__half2*)(base + (rl + 8) * 40 + cc) = s0v[mt][nt][1];
                }
            }
            __syncthreads();
        }

        // ---- layer 5 (N=128) + fused output head --------------------------
        {
            const __half* nH = (t < 14) ? WhL[0] : nullptr;
            const __half* nL = (t < 14) ? WlL[0] : nullptr;

            float acc[2][4][4];
#pragma unroll
            for (int i = 0; i < 2; i++)
#pragma unroll
                for (int j = 0; j < 4; j++)
#pragma unroll
                    for (int q = 0; q < 4; q++) acc[i][j][q] = 0.f;

            gemm16(sA, sW, WhL[3], WlL[3], nH, nL, pre, tid, lane, wm, wn, acc);

#pragma unroll
            for (int mt = 0; mt < 2; mt++) {
                int rl = rowL + mt * 16;
                int r = m0 + rl;
#pragma unroll
                for (int nt = 0; nt < 4; nt++) {
                    int c = colL + nt * 8;
                    size_t gi0 = (size_t)r * 128 + c;
                    size_t gi1 = gi0 + (size_t)8 * 128;
                    float2 bb = *(const float2*)(b5 + c);
                    float2 mp0 = *(float2*)(mem5 + gi0);
                    float2 mp1 = *(float2*)(mem5 + gi1);
                    float cv0 = acc[mt][nt][0] + bb.x;
                    float cv1 = acc[mt][nt][1] + bb.y;
                    float cv2 = acc[mt][nt][2] + bb.x;
                    float cv3 = acc[mt][nt][3] + bb.y;
                    float n0v = 0.82f * mp0.x + cv0 - (mp0.x > THRV ? THRV : 0.f);
                    float n1v = 0.82f * mp0.y + cv1 - (mp0.y > THRV ? THRV : 0.f);
                    float n2v = 0.82f * mp1.x + cv2 - (mp1.x > THRV ? THRV : 0.f);
                    float n3v = 0.82f * mp1.y + cv3 - (mp1.y > THRV ? THRV : 0.f);
                    *(float2*)(mem5 + gi0) = make_float2(n0v, n1v);
                    *(float2*)(mem5 + gi1) = make_float2(n2v, n3v);
                    int cc = c & 31;
                    __half* base = sA + (c >> 5) * T_H;
                    *(__half2*)(base + rl * 40 + cc) =
                        __floats2half2_rn(n0v > THRV ? 1.f : 0.f,
                                          n1v > THRV ? 1.f : 0.f);
                    *(__half2*)(base + (rl + 8) * 40 + cc) =
                        __floats2half2_rn(n2v > THRV ? 1.f : 0.f,
                                          n3v > THRV ? 1.f : 0.f);
                }
            }
            __syncthreads();

            if (tid < 128) {
                float s0 = b60, s1 = b61, s2v = b62;
#pragma unroll
                for (int ch = 0; ch < 4; ch++) {
                    const __half* sr = sA + ch * T_H + tid * 40;
#pragma unroll
                    for (int k = 0; k < 32; k++) {
                        float v = __half2float(sr[k]);
                        int x = ch * 32 + k;
                        s0 = fmaf(v, ws[x], s0);
                        s1 = fmaf(v, ws[128 + x], s1);
                        s2v = fmaf(v, ws[256 + x], s2v);
                    }
                }
                o0 += s0; o1 += s1; o2 += s2v;
            }
            __syncthreads();   // head done before next step's A staging
        }
    }

    if (tid < 128) {
        int b = m0 + tid;
        const float inv = 1.f / 15.f;
        out[b * 3 + 0] = o0 * inv;
        out[b * 3 + 1] = o1 * inv;
        out[b * 3 + 2] = o2 * inv;
    }
}

// ---------------- launch --------------------------------------------------
extern "C" void kernel_launch(void* const* d_in, const int* in_sizes, int n_in,
                              void* d_out, int out_size) {
    const float* x  = (const float*)d_in[0];
    const float* W1 = (const float*)d_in[1];
    const float* b1 = (const float*)d_in[2];
    const float* W2 = (const float*)d_in[3];
    const float* b2 = (const float*)d_in[4];
    const float* W3 = (const float*)d_in[5];
    const float* b3 = (const float*)d_in[6];
    const float* W4 = (const float*)d_in[7];
    const float* b4 = (const float*)d_in[8];
    const float* W5 = (const float*)d_in[9];
    const float* b5 = (const float*)d_in[10];
    const float* W6 = (const float*)d_in[11];
    const float* b6 = (const float*)d_in[12];
    float* out = (float*)d_out;

    __half *p_spk1, *p_Wh, *p_Wl;
    float *p_mem2, *p_mem3, *p_mem4, *p_mem5;
    cudaGetSymbolAddress((void**)&p_spk1, g_spk1);
    cudaGetSymbolAddress((void**)&p_Wh, g_Wh);
    cudaGetSymbolAddress((void**)&p_Wl, g_Wl);
    cudaGetSymbolAddress((void**)&p_mem2, g_mem2);
    cudaGetSymbolAddress((void**)&p_mem3, g_mem3);
    cudaGetSymbolAddress((void**)&p_mem4, g_mem4);
    cudaGetSymbolAddress((void**)&p_mem5, g_mem5);

    cudaFuncSetAttribute(k_snn, cudaFuncAttributeMaxDynamicSharedMemorySize, SMEMT);

    k_setup<<<2048, 256>>>(x, W1, b1, W2, W3, W4, W5);
    k_snn<<<NB / 128, 512, SMEMT>>>(p_spk1, p_Wh, p_Wl, b2, b3, b4, b5,
                                    p_mem2, p_mem3, p_mem4, p_mem5,
                                    W6, b6, out);
}